// round 14
// baseline (speedup 1.0000x reference)
#include <cuda_runtime.h>
#include <cstdint>

// Problem shapes (fixed by the dataset)
constexpr int Bdim = 8;
constexpr int T    = 512;
constexpr int D    = 1024;
constexpr int E    = 64;

// Tiling: CTA 128x128, 16 warps (4M x 4N), warp tile 32x32, BK=64, 3 stages
constexpr int BM = 128;
constexpr int BN = 128;
constexpr int BK = 64;
constexpr int STAGES = 3;
constexpr int NSEG = 2 * (D / BK);   // 32 segments (2 experts x 16 slabs)
constexpr int THREADS = 512;

constexpr int AS_STRIDE = BK + 4;    // 68
constexpr int BS_STRIDE = BN + 8;    // 136
constexpr int A_STAGE = BM * AS_STRIDE;   // 8704 floats
constexpr int B_STAGE = BK * BS_STRIDE;   // 8704 floats
constexpr int SMEM_BYTES = STAGES * (A_STAGE + B_STAGE) * 4;  // 208896

// RNA-rounded copy of x (tf32-exact; raw LDS feed == RNA rounding for A)
__device__ float g_x_round[(size_t)Bdim * T * D];

__device__ __forceinline__ void cp16(float* smem_ptr, const float* gmem_ptr) {
    uint32_t s = (uint32_t)__cvta_generic_to_shared(smem_ptr);
    asm volatile("cp.async.cg.shared.global [%0], [%1], 16;" :: "r"(s), "l"(gmem_ptr));
}
__device__ __forceinline__ uint32_t f2tf32(float f) {
    uint32_t r;
    asm("cvt.rna.tf32.f32 %0, %1;" : "=r"(r) : "f"(f));
    return r;
}
__device__ __forceinline__ void mma_tf32(float* c, const uint32_t* a, const uint32_t* b) {
    asm volatile(
        "mma.sync.aligned.m16n8k8.row.col.f32.tf32.tf32.f32 "
        "{%0,%1,%2,%3}, {%4,%5,%6,%7}, {%8,%9}, {%0,%1,%2,%3};\n"
        : "+f"(c[0]), "+f"(c[1]), "+f"(c[2]), "+f"(c[3])
        : "r"(a[0]), "r"(a[1]), "r"(a[2]), "r"(a[3]), "r"(b[0]), "r"(b[1]));
}

// idx dtype auto-detect (proven in R3): int32 unless all high words zero.
__device__ __forceinline__ int load_expert_idx(const void* idx_raw, int pos) {
    const int* p32 = (const int*)idx_raw;
    bool is64 = true;
    #pragma unroll
    for (int j = 1; j < 16; j += 2) is64 &= (p32[j] == 0);
    int e = is64 ? p32[2 * pos] : p32[pos];
    return min(max(e, 0), E - 1);
}

// Pre-kernel: RNA-round x once
__global__ void round_x_kernel(const float* __restrict__ x) {
    const int n4 = (Bdim * T * D) / 4;
    const float4* src = (const float4*)x;
    float4* dst = (float4*)g_x_round;
    for (int i = blockIdx.x * blockDim.x + threadIdx.x; i < n4; i += gridDim.x * blockDim.x) {
        float4 v = src[i];
        v.x = __uint_as_float(f2tf32(v.x));
        v.y = __uint_as_float(f2tf32(v.y));
        v.z = __uint_as_float(f2tf32(v.z));
        v.w = __uint_as_float(f2tf32(v.w));
        dst[i] = v;
    }
}

extern __shared__ float smem[];

__global__ void __launch_bounds__(THREADS, 1)
expertbank_kernel(const float* __restrict__ w,
                  const float* __restrict__ Wb,
                  const float* __restrict__ bb,
                  const void*  __restrict__ idx,
                  float* __restrict__ out)
{
    const int tn = blockIdx.x;   // N tile (0..7)
    const int tm = blockIdx.y;   // M tile (0..3)
    const int b  = blockIdx.z;   // batch

    const int tid  = threadIdx.x;
    const int lane = tid & 31;
    const int warp = tid >> 5;
    const int wm = warp & 3;     // warp row (4 in M)
    const int wn = warp >> 2;    // warp col (4 in N)

    const float* xblk = g_x_round + ((size_t)b * T + (size_t)tm * BM) * D;

    const int e0 = load_expert_idx(idx, b * 2 + 0);
    const int e1 = load_expert_idx(idx, b * 2 + 1);
    const float w0 = w[b * 2 + 0];
    const float w1 = w[b * 2 + 1];
    const float* Wp[2] = { Wb + (size_t)e0 * D * D + (size_t)tn * BN,
                           Wb + (size_t)e1 * D * D + (size_t)tn * BN };

    float* As0 = smem;                    // STAGES x [BM][AS_STRIDE]
    float* Bs0 = smem + STAGES * A_STAGE; // STAGES x [BK][BS_STRIDE]

    // warp tile 32x32: 2 m-frags x 4 n-frags
    float out_acc[2][4][4];
    float acc[2][4][4];
    #pragma unroll
    for (int mi = 0; mi < 2; ++mi)
        #pragma unroll
        for (int ni = 0; ni < 4; ++ni)
            #pragma unroll
            for (int j = 0; j < 4; ++j) {
                out_acc[mi][ni][j] = 0.f;
                acc[mi][ni][j] = 0.f;
            }

    const int ar = wm * 32 + (lane >> 2);   // A fragment base row
    const int bc = wn * 32 + (lane >> 2);   // B fragment base col

    auto load_ab = [&](int s, int stage) {
        float* Ad = As0 + stage * A_STAGE;
        const float* Ag = xblk + (s & 15) * BK;
        #pragma unroll
        for (int i = 0; i < 4; ++i) {
            int lin = tid + i * THREADS;          // 0..2047
            int m  = lin >> 4;                    // 128 rows, 16 float4/row
            int kv = (lin & 15) << 2;
            cp16(Ad + m * AS_STRIDE + kv, Ag + (size_t)m * D + kv);
        }
        float* Bd = Bs0 + stage * B_STAGE;
        const float* Bg = Wp[s >> 4] + (size_t)(s & 15) * BK * D;
        #pragma unroll
        for (int i = 0; i < 4; ++i) {
            int lin = tid + i * THREADS;          // 0..2047
            int k  = lin >> 5;                    // 64 rows, 32 float4/row
            int nv = (lin & 31) << 2;
            cp16(Bd + k * BS_STRIDE + nv, Bg + (size_t)k * D + nv);
        }
        asm volatile("cp.async.commit_group;" ::: "memory");
    };

    // prologue: stages 0 and 1 in flight
    load_ab(0, 0);
    load_ab(1, 1);

    for (int s = 0; s < NSEG; ++s) {
        if (s >= NSEG - 2)
            asm volatile("cp.async.wait_group 0;" ::: "memory");
        else
            asm volatile("cp.async.wait_group 1;" ::: "memory");
        __syncthreads();

        if (s + 2 < NSEG) load_ab(s + 2, (s + 2) % STAGES);

        const float* Ab = As0 + (s % STAGES) * A_STAGE;
        const float* Bb = Bs0 + (s % STAGES) * B_STAGE;

        // fragment double-buffer across the 8 kk steps
        uint32_t af[2][2][4];   // [buf][mi][4]
        uint32_t bf[2][4][2];   // [buf][ni][2]

        auto ldfrag = [&](int kk, int fb) {
            const int c = kk * 8 + (lane & 3);
            #pragma unroll
            for (int mi = 0; mi < 2; ++mi) {
                const float* A0 = Ab + (ar + mi * 16) * AS_STRIDE + c;
                af[fb][mi][0] = __float_as_uint(A0[0]);
                af[fb][mi][1] = __float_as_uint(A0[8 * AS_STRIDE]);
                af[fb][mi][2] = __float_as_uint(A0[4]);
                af[fb][mi][3] = __float_as_uint(A0[8 * AS_STRIDE + 4]);
            }
            #pragma unroll
            for (int ni = 0; ni < 4; ++ni) {
                const float* B0 = Bb + c * BS_STRIDE + bc + ni * 8;
                bf[fb][ni][0] = __float_as_uint(B0[0]);
                bf[fb][ni][1] = __float_as_uint(B0[4 * BS_STRIDE]);
            }
        };

        ldfrag(0, 0);
        #pragma unroll
        for (int kk = 0; kk < BK / 8; ++kk) {
            const int cur = kk & 1;
            if (kk + 1 < BK / 8) ldfrag(kk + 1, cur ^ 1);
            #pragma unroll
            for (int mi = 0; mi < 2; ++mi)
                #pragma unroll
                for (int ni = 0; ni < 4; ++ni)
                    mma_tf32(acc[mi][ni], af[cur][mi], bf[cur][ni]);
        }

        // expert-0 boundary: fold into out_acc, reset acc (thread-local)
        if (s == (NSEG / 2) - 1) {
            const float* bp = bb + (size_t)e0 * D + (size_t)tn * BN;
            #pragma unroll
            for (int mi = 0; mi < 2; ++mi)
                #pragma unroll
                for (int ni = 0; ni < 4; ++ni) {
                    int col = wn * 32 + ni * 8 + (lane & 3) * 2;
                    float b0v = bp[col], b1v = bp[col + 1];
                    out_acc[mi][ni][0] = w0 * fmaxf(acc[mi][ni][0] + b0v, 0.f);
                    out_acc[mi][ni][1] = w0 * fmaxf(acc[mi][ni][1] + b1v, 0.f);
                    out_acc[mi][ni][2] = w0 * fmaxf(acc[mi][ni][2] + b0v, 0.f);
                    out_acc[mi][ni][3] = w0 * fmaxf(acc[mi][ni][3] + b1v, 0.f);
                    acc[mi][ni][0] = 0.f; acc[mi][ni][1] = 0.f;
                    acc[mi][ni][2] = 0.f; acc[mi][ni][3] = 0.f;
                }
        }
    }

    // expert-1 fold + store
    {
        const float* bp = bb + (size_t)e1 * D + (size_t)tn * BN;
        float* ob = out + ((size_t)b * T + (size_t)tm * BM) * D + (size_t)tn * BN;
        #pragma unroll
        for (int mi = 0; mi < 2; ++mi)
            #pragma unroll
            for (int ni = 0; ni < 4; ++ni) {
                int col = wn * 32 + ni * 8 + (lane & 3) * 2;
                float b0v = bp[col], b1v = bp[col + 1];
                float v00 = out_acc[mi][ni][0] + w1 * fmaxf(acc[mi][ni][0] + b0v, 0.f);
                float v01 = out_acc[mi][ni][1] + w1 * fmaxf(acc[mi][ni][1] + b1v, 0.f);
                float v10 = out_acc[mi][ni][2] + w1 * fmaxf(acc[mi][ni][2] + b0v, 0.f);
                float v11 = out_acc[mi][ni][3] + w1 * fmaxf(acc[mi][ni][3] + b1v, 0.f);
                int r0 = wm * 32 + mi * 16 + (lane >> 2);
                *reinterpret_cast<float2*>(&ob[(size_t)r0 * D + col]) = make_float2(v00, v01);
                *reinterpret_cast<float2*>(&ob[(size_t)(r0 + 8) * D + col]) = make_float2(v10, v11);
            }
    }
}

extern "C" void kernel_launch(void* const* d_in, const int* in_sizes, int n_in,
                              void* d_out, int out_size) {
    const float* x   = (const float*)d_in[0];
    const float* w   = (const float*)d_in[1];
    const float* Wb  = (const float*)d_in[2];
    const float* bb  = (const float*)d_in[3];
    const void*  idx = (const void*)d_in[4];
    float* out = (float*)d_out;

    round_x_kernel<<<2048, 256>>>(x);

    cudaFuncSetAttribute(expertbank_kernel,
                         cudaFuncAttributeMaxDynamicSharedMemorySize, SMEM_BYTES);
    dim3 grid(D / BN, T / BM, Bdim);  // (8, 4, 8) = 256 blocks
    expertbank_kernel<<<grid, THREADS, SMEM_BYTES>>>(w, Wb, bb, idx, out);
}

// round 15
// speedup vs baseline: 1.6272x; 1.6272x over previous
#include <cuda_runtime.h>
#include <cuda_fp16.h>
#include <cstdint>

// Problem shapes (fixed by the dataset)
constexpr int Bdim = 8;
constexpr int T    = 512;
constexpr int D    = 1024;
constexpr int E    = 64;

// Tiling: CTA 128x128, 8 warps (4M x 2N), warp tile 32x64, BK=64
constexpr int BM = 128;
constexpr int BN = 128;
constexpr int BK = 64;
constexpr int NSEG = 2 * (D / BK);   // 32 segments (2 experts x 16 slabs)
constexpr int THREADS = 256;

// SMEM layout (bytes). A: fp16 [128 rows][64 k], row stride 144B (8B pad).
// B: fp16 [64 k rows][128 n], row stride 272B (16B pad). A triple, B double buffered.
constexpr int ASTR   = 144;
constexpr int A_STAGE = BM * ASTR;        // 18432
constexpr int BSTR   = 272;
constexpr int B_STAGE = BK * BSTR;        // 17408
constexpr int SM_A = 0;
constexpr int SM_B = 3 * A_STAGE;         // 55296
constexpr int SMEM_BYTES = SM_B + 2 * B_STAGE;  // 90112

// fp16 (RNE) copy of x
__device__ __half g_x_half[(size_t)Bdim * T * D];

__device__ __forceinline__ void cp16(uint32_t smem_addr, const void* gmem_ptr) {
    asm volatile("cp.async.cg.shared.global [%0], [%1], 16;" :: "r"(smem_addr), "l"(gmem_ptr));
}
__device__ __forceinline__ void ldsm4(uint32_t* r, uint32_t addr) {
    asm volatile("ldmatrix.sync.aligned.m8n8.x4.shared.b16 {%0,%1,%2,%3}, [%4];"
                 : "=r"(r[0]), "=r"(r[1]), "=r"(r[2]), "=r"(r[3]) : "r"(addr));
}
__device__ __forceinline__ void ldsm4t(uint32_t* r, uint32_t addr) {
    asm volatile("ldmatrix.sync.aligned.m8n8.x4.trans.shared.b16 {%0,%1,%2,%3}, [%4];"
                 : "=r"(r[0]), "=r"(r[1]), "=r"(r[2]), "=r"(r[3]) : "r"(addr));
}
__device__ __forceinline__ void mma_f16(float* c, const uint32_t* a, uint32_t b0, uint32_t b1) {
    asm volatile(
        "mma.sync.aligned.m16n8k16.row.col.f32.f16.f16.f32 "
        "{%0,%1,%2,%3}, {%4,%5,%6,%7}, {%8,%9}, {%0,%1,%2,%3};\n"
        : "+f"(c[0]), "+f"(c[1]), "+f"(c[2]), "+f"(c[3])
        : "r"(a[0]), "r"(a[1]), "r"(a[2]), "r"(a[3]), "r"(b0), "r"(b1));
}

// idx dtype auto-detect (proven in R3): int32 unless all high words zero.
__device__ __forceinline__ int load_expert_idx(const void* idx_raw, int pos) {
    const int* p32 = (const int*)idx_raw;
    bool is64 = true;
    #pragma unroll
    for (int j = 1; j < 16; j += 2) is64 &= (p32[j] == 0);
    int e = is64 ? p32[2 * pos] : p32[pos];
    return min(max(e, 0), E - 1);
}

// Pre-kernel: RNE-round x to fp16 once
__global__ void round_x_half(const float* __restrict__ x) {
    const int n4 = (Bdim * T * D) / 4;
    const float4* src = (const float4*)x;
    uint2* dst = (uint2*)g_x_half;   // 4 halves = 8 bytes
    for (int i = blockIdx.x * blockDim.x + threadIdx.x; i < n4; i += gridDim.x * blockDim.x) {
        float4 v = src[i];
        __half2 h0 = __floats2half2_rn(v.x, v.y);
        __half2 h1 = __floats2half2_rn(v.z, v.w);
        uint2 u;
        u.x = *reinterpret_cast<uint32_t*>(&h0);
        u.y = *reinterpret_cast<uint32_t*>(&h1);
        dst[i] = u;
    }
}

extern __shared__ char smem[];

__global__ void __launch_bounds__(THREADS, 1)
expertbank_kernel(const float* __restrict__ w,
                  const float* __restrict__ Wb,
                  const float* __restrict__ bb,
                  const void*  __restrict__ idx,
                  float* __restrict__ out)
{
    const int tn = blockIdx.x;   // N tile (0..7)
    const int tm = blockIdx.y;   // M tile (0..3)
    const int b  = blockIdx.z;   // batch

    const int tid  = threadIdx.x;
    const int lane = tid & 31;
    const int warp = tid >> 5;
    const int wm = warp & 3;     // warp row (4 in M)
    const int wn = warp >> 2;    // warp col (2 in N)

    const uint32_t sbase = (uint32_t)__cvta_generic_to_shared(smem);
    const uint32_t smA = sbase + SM_A;
    const uint32_t smB = sbase + SM_B;

    const __half* xblk = g_x_half + ((size_t)b * T + (size_t)tm * BM) * D;

    const int e0 = load_expert_idx(idx, b * 2 + 0);
    const int e1 = load_expert_idx(idx, b * 2 + 1);
    const float w0 = w[b * 2 + 0];
    const float w1 = w[b * 2 + 1];
    const float* Wp[2] = { Wb + (size_t)e0 * D * D + (size_t)tn * BN,
                           Wb + (size_t)e1 * D * D + (size_t)tn * BN };

    float out_acc[2][8][4];
    float acc[2][8][4];
    #pragma unroll
    for (int mi = 0; mi < 2; ++mi)
        #pragma unroll
        for (int ni = 0; ni < 8; ++ni)
            #pragma unroll
            for (int j = 0; j < 4; ++j) {
                out_acc[mi][ni][j] = 0.f;
                acc[mi][ni][j] = 0.f;
            }

    // LDSM per-lane offsets (within a stage buffer)
    // A (non-trans): lanes 0-7 rows 0-7, 8-15 rows 8-15, 16-23 rows 0-7 (+16B k), 24-31 rows 8-15 (+16B)
    const uint32_t aoff = (uint32_t)((wm * 32 + (lane & 15)) * ASTR + (lane >> 4) * 16);
    // B (trans): lanes 0-15 rows k0..k0+15 at n-block, lanes 16-31 same rows at n-block+8 halves
    const uint32_t boff = (uint32_t)((lane & 15) * BSTR + (wn * 64 + (lane >> 4) * 8) * 2);

    float4 breg[8];   // B gmem prefetch registers (f32)

    auto ldgB = [&](int s) {
        const float* Bg = Wp[s >> 4] + (size_t)(s & 15) * BK * D;
        #pragma unroll
        for (int i = 0; i < 8; ++i) {
            int lin = tid + i * THREADS;          // 0..2047
            int k   = lin >> 5;                   // 64 rows
            int nf4 = lin & 31;                   // 32 float4 per row
            breg[i] = *(const float4*)(Bg + (size_t)k * D + nf4 * 4);
        }
    };
    auto stsB = [&](int buf) {
        uint32_t base = smB + buf * B_STAGE;
        #pragma unroll
        for (int i = 0; i < 8; ++i) {
            int lin = tid + i * THREADS;
            int k   = lin >> 5;
            int nf4 = lin & 31;
            __half2 h0 = __floats2half2_rn(breg[i].x, breg[i].y);
            __half2 h1 = __floats2half2_rn(breg[i].z, breg[i].w);
            uint32_t u0 = *reinterpret_cast<uint32_t*>(&h0);
            uint32_t u1 = *reinterpret_cast<uint32_t*>(&h1);
            asm volatile("st.shared.v2.b32 [%0], {%1, %2};"
                         :: "r"(base + k * BSTR + nf4 * 8), "r"(u0), "r"(u1));
        }
    };
    auto cpA = [&](int s, int stage) {
        uint32_t base = smA + stage * A_STAGE;
        const __half* Ag = xblk + (s & 15) * BK;
        #pragma unroll
        for (int i = 0; i < 4; ++i) {
            int lin = tid + i * THREADS;          // 0..1023
            int m  = lin >> 3;                    // 128 rows
            int ch = lin & 7;                     // 8 x 16B chunks per row
            cp16(base + m * ASTR + ch * 16, Ag + (size_t)m * D + ch * 8);
        }
        asm volatile("cp.async.commit_group;" ::: "memory");
    };

    // prologue
    ldgB(0);
    cpA(0, 0);
    cpA(1, 1);

    for (int s = 0; s < NSEG; ++s) {
        if (s >= NSEG - 1)
            asm volatile("cp.async.wait_group 0;" ::: "memory");
        else
            asm volatile("cp.async.wait_group 1;" ::: "memory");
        __syncthreads();                       // A(s) ready; B buf (s&1) free

        stsB(s & 1);                           // convert+store B(s)
        if (s + 1 < NSEG) ldgB(s + 1);
        if (s + 2 < NSEG) cpA(s + 2, (s + 2) % 3);
        __syncthreads();                       // B(s) visible

        const uint32_t Ab = smA + (s % 3) * A_STAGE + aoff;
        const uint32_t Bb = smB + (s & 1) * B_STAGE + boff;

        #pragma unroll
        for (int kk = 0; kk < BK / 16; ++kk) {
            uint32_t a[2][4], bq[4][4];
            ldsm4(a[0], Ab + kk * 32);
            ldsm4(a[1], Ab + 16 * ASTR + kk * 32);
            #pragma unroll
            for (int nip = 0; nip < 4; ++nip)
                ldsm4t(bq[nip], Bb + nip * 32 + kk * 16 * BSTR);
            #pragma unroll
            for (int mi = 0; mi < 2; ++mi)
                #pragma unroll
                for (int ni = 0; ni < 8; ++ni) {
                    const int nip = ni >> 1, h = (ni & 1) * 2;
                    mma_f16(acc[mi][ni], a[mi], bq[nip][h], bq[nip][h + 1]);
                }
        }

        // expert-0 boundary: fold into out_acc, reset acc (thread-local)
        if (s == (NSEG / 2) - 1) {
            const float* bp = bb + (size_t)e0 * D + (size_t)tn * BN;
            #pragma unroll
            for (int mi = 0; mi < 2; ++mi)
                #pragma unroll
                for (int ni = 0; ni < 8; ++ni) {
                    int col = wn * 64 + ni * 8 + (lane & 3) * 2;
                    float b0v = bp[col], b1v = bp[col + 1];
                    out_acc[mi][ni][0] = w0 * fmaxf(acc[mi][ni][0] + b0v, 0.f);
                    out_acc[mi][ni][1] = w0 * fmaxf(acc[mi][ni][1] + b1v, 0.f);
                    out_acc[mi][ni][2] = w0 * fmaxf(acc[mi][ni][2] + b0v, 0.f);
                    out_acc[mi][ni][3] = w0 * fmaxf(acc[mi][ni][3] + b1v, 0.f);
                    acc[mi][ni][0] = 0.f; acc[mi][ni][1] = 0.f;
                    acc[mi][ni][2] = 0.f; acc[mi][ni][3] = 0.f;
                }
        }
    }

    // expert-1 fold + store
    {
        const float* bp = bb + (size_t)e1 * D + (size_t)tn * BN;
        float* ob = out + ((size_t)b * T + (size_t)tm * BM) * D + (size_t)tn * BN;
        #pragma unroll
        for (int mi = 0; mi < 2; ++mi)
            #pragma unroll
            for (int ni = 0; ni < 8; ++ni) {
                int col = wn * 64 + ni * 8 + (lane & 3) * 2;
                float b0v = bp[col], b1v = bp[col + 1];
                float v00 = out_acc[mi][ni][0] + w1 * fmaxf(acc[mi][ni][0] + b0v, 0.f);
                float v01 = out_acc[mi][ni][1] + w1 * fmaxf(acc[mi][ni][1] + b1v, 0.f);
                float v10 = out_acc[mi][ni][2] + w1 * fmaxf(acc[mi][ni][2] + b0v, 0.f);
                float v11 = out_acc[mi][ni][3] + w1 * fmaxf(acc[mi][ni][3] + b1v, 0.f);
                int r0 = wm * 32 + mi * 16 + (lane >> 2);
                *reinterpret_cast<float2*>(&ob[(size_t)r0 * D + col]) = make_float2(v00, v01);
                *reinterpret_cast<float2*>(&ob[(size_t)(r0 + 8) * D + col]) = make_float2(v10, v11);
            }
    }
}

extern "C" void kernel_launch(void* const* d_in, const int* in_sizes, int n_in,
                              void* d_out, int out_size) {
    const float* x   = (const float*)d_in[0];
    const float* w   = (const float*)d_in[1];
    const float* Wb  = (const float*)d_in[2];
    const float* bb  = (const float*)d_in[3];
    const void*  idx = (const void*)d_in[4];
    float* out = (float*)d_out;

    round_x_half<<<2048, 256>>>(x);

    cudaFuncSetAttribute(expertbank_kernel,
                         cudaFuncAttributeMaxDynamicSharedMemorySize, SMEM_BYTES);
    dim3 grid(D / BN, T / BM, Bdim);  // (8, 4, 8) = 256 blocks
    expertbank_kernel<<<grid, THREADS, SMEM_BYTES>>>(w, Wb, bb, idx, out);
}

// round 16
// speedup vs baseline: 1.7646x; 1.0844x over previous
#include <cuda_runtime.h>
#include <cuda_fp16.h>
#include <cstdint>

// Problem shapes (fixed by the dataset)
constexpr int Bdim = 8;
constexpr int T    = 512;
constexpr int D    = 1024;
constexpr int E    = 64;

// Tiling: CTA 128x128, 8 warps (4M x 2N), warp tile 32x64, BK=64
constexpr int BM = 128;
constexpr int BN = 128;
constexpr int BK = 64;
constexpr int NSEG = 2 * (D / BK);   // 32 segments (2 experts x 16 slabs)
constexpr int THREADS = 256;

// SMEM layout (bytes). A: fp16 [128 rows][64 k], row stride 144B (8B pad).
// B: fp16 [64 k rows][128 n], row stride 272B (16B pad). A triple, B double buffered.
constexpr int ASTR   = 144;
constexpr int A_STAGE = BM * ASTR;        // 18432
constexpr int BSTR   = 272;
constexpr int B_STAGE = BK * BSTR;        // 17408
constexpr int SM_A = 0;
constexpr int SM_B = 3 * A_STAGE;         // 55296
constexpr int SMEM_BYTES = SM_B + 2 * B_STAGE;  // 90112

// fp16 (RNE) copy of x
__device__ __half g_x_half[(size_t)Bdim * T * D];

__device__ __forceinline__ void cp16(uint32_t smem_addr, const void* gmem_ptr) {
    asm volatile("cp.async.cg.shared.global [%0], [%1], 16;" :: "r"(smem_addr), "l"(gmem_ptr));
}
__device__ __forceinline__ void ldsm4(uint32_t* r, uint32_t addr) {
    asm volatile("ldmatrix.sync.aligned.m8n8.x4.shared.b16 {%0,%1,%2,%3}, [%4];"
                 : "=r"(r[0]), "=r"(r[1]), "=r"(r[2]), "=r"(r[3]) : "r"(addr));
}
__device__ __forceinline__ void ldsm4t(uint32_t* r, uint32_t addr) {
    asm volatile("ldmatrix.sync.aligned.m8n8.x4.trans.shared.b16 {%0,%1,%2,%3}, [%4];"
                 : "=r"(r[0]), "=r"(r[1]), "=r"(r[2]), "=r"(r[3]) : "r"(addr));
}
__device__ __forceinline__ void mma_f16(float* c, const uint32_t* a, uint32_t b0, uint32_t b1) {
    asm volatile(
        "mma.sync.aligned.m16n8k16.row.col.f32.f16.f16.f32 "
        "{%0,%1,%2,%3}, {%4,%5,%6,%7}, {%8,%9}, {%0,%1,%2,%3};\n"
        : "+f"(c[0]), "+f"(c[1]), "+f"(c[2]), "+f"(c[3])
        : "r"(a[0]), "r"(a[1]), "r"(a[2]), "r"(a[3]), "r"(b0), "r"(b1));
}

// idx dtype auto-detect (proven in R3): int32 unless all high words zero.
__device__ __forceinline__ int load_expert_idx(const void* idx_raw, int pos) {
    const int* p32 = (const int*)idx_raw;
    bool is64 = true;
    #pragma unroll
    for (int j = 1; j < 16; j += 2) is64 &= (p32[j] == 0);
    int e = is64 ? p32[2 * pos] : p32[pos];
    return min(max(e, 0), E - 1);
}

// Pre-kernel: RNE-round x to fp16 once
__global__ void round_x_half(const float* __restrict__ x) {
    const int n4 = (Bdim * T * D) / 4;
    const float4* src = (const float4*)x;
    uint2* dst = (uint2*)g_x_half;
    for (int i = blockIdx.x * blockDim.x + threadIdx.x; i < n4; i += gridDim.x * blockDim.x) {
        float4 v = src[i];
        __half2 h0 = __floats2half2_rn(v.x, v.y);
        __half2 h1 = __floats2half2_rn(v.z, v.w);
        uint2 u;
        u.x = *reinterpret_cast<uint32_t*>(&h0);
        u.y = *reinterpret_cast<uint32_t*>(&h1);
        dst[i] = u;
    }
}

extern __shared__ char smem[];

__global__ void __launch_bounds__(THREADS, 1)
expertbank_kernel(const float* __restrict__ w,
                  const float* __restrict__ Wb,
                  const float* __restrict__ bb,
                  const void*  __restrict__ idx,
                  float* __restrict__ out)
{
    const int tn = blockIdx.x;   // N tile (0..7)
    const int tm = blockIdx.y;   // M tile (0..3)
    const int b  = blockIdx.z;   // batch

    const int tid  = threadIdx.x;
    const int lane = tid & 31;
    const int warp = tid >> 5;
    const int wm = warp & 3;     // warp row (4 in M)
    const int wn = warp >> 2;    // warp col (2 in N)

    const uint32_t sbase = (uint32_t)__cvta_generic_to_shared(smem);
    const uint32_t smA = sbase + SM_A;
    const uint32_t smB = sbase + SM_B;

    const __half* xblk = g_x_half + ((size_t)b * T + (size_t)tm * BM) * D;

    const int e0 = load_expert_idx(idx, b * 2 + 0);
    const int e1 = load_expert_idx(idx, b * 2 + 1);
    const float w0 = w[b * 2 + 0];
    const float w1 = w[b * 2 + 1];
    const float* Wp[2] = { Wb + (size_t)e0 * D * D + (size_t)tn * BN,
                           Wb + (size_t)e1 * D * D + (size_t)tn * BN };

    float out_acc[2][8][4];
    float acc[2][8][4];
    #pragma unroll
    for (int mi = 0; mi < 2; ++mi)
        #pragma unroll
        for (int ni = 0; ni < 8; ++ni)
            #pragma unroll
            for (int j = 0; j < 4; ++j) {
                out_acc[mi][ni][j] = 0.f;
                acc[mi][ni][j] = 0.f;
            }

    // LDSM per-lane offsets (within a stage buffer)
    const uint32_t aoff = (uint32_t)((wm * 32 + (lane & 15)) * ASTR + (lane >> 4) * 16);
    const uint32_t boff = (uint32_t)((lane & 15) * BSTR + (wn * 64 + (lane >> 4) * 8) * 2);

    float4 breg[8];   // B gmem prefetch registers (f32)

    auto ldgB = [&](int s) {
        const float* Bg = Wp[s >> 4] + (size_t)(s & 15) * BK * D;
        #pragma unroll
        for (int i = 0; i < 8; ++i) {
            int lin = tid + i * THREADS;          // 0..2047
            int k   = lin >> 5;                   // 64 rows
            int nf4 = lin & 31;                   // 32 float4 per row
            breg[i] = *(const float4*)(Bg + (size_t)k * D + nf4 * 4);
        }
    };
    auto stsB = [&](int buf) {
        uint32_t base = smB + buf * B_STAGE;
        #pragma unroll
        for (int i = 0; i < 8; ++i) {
            int lin = tid + i * THREADS;
            int k   = lin >> 5;
            int nf4 = lin & 31;
            __half2 h0 = __floats2half2_rn(breg[i].x, breg[i].y);
            __half2 h1 = __floats2half2_rn(breg[i].z, breg[i].w);
            uint32_t u0 = *reinterpret_cast<uint32_t*>(&h0);
            uint32_t u1 = *reinterpret_cast<uint32_t*>(&h1);
            asm volatile("st.shared.v2.b32 [%0], {%1, %2};"
                         :: "r"(base + k * BSTR + nf4 * 8), "r"(u0), "r"(u1));
        }
    };
    auto cpA = [&](int s, int stage) {
        uint32_t base = smA + stage * A_STAGE;
        const __half* Ag = xblk + (s & 15) * BK;
        #pragma unroll
        for (int i = 0; i < 4; ++i) {
            int lin = tid + i * THREADS;          // 0..1023
            int m  = lin >> 3;                    // 128 rows
            int ch = lin & 7;                     // 8 x 16B chunks per row
            cp16(base + m * ASTR + ch * 16, Ag + (size_t)m * D + ch * 8);
        }
        asm volatile("cp.async.commit_group;" ::: "memory");
    };

    // prologue: B(0) converted into buf0 before loop; B(1) prefetched to regs;
    // A(0), A(1) in flight.
    ldgB(0);
    stsB(0);
    ldgB(1);
    cpA(0, 0);
    cpA(1, 1);

    for (int s = 0; s < NSEG; ++s) {
        if (s >= NSEG - 1)
            asm volatile("cp.async.wait_group 0;" ::: "memory");
        else
            asm volatile("cp.async.wait_group 1;" ::: "memory");
        __syncthreads();   // A(s) ready; B(s) (stored last iter / prologue) visible

        const uint32_t Ab = smA + (s % 3) * A_STAGE + aoff;
        const uint32_t Bb = smB + (s & 1) * B_STAGE + boff;

        // ---- math for segment s (critical path: LDSM + MMA only)
        #pragma unroll
        for (int kk = 0; kk < BK / 16; ++kk) {
            uint32_t a[2][4], bq[4][4];
            ldsm4(a[0], Ab + kk * 32);
            ldsm4(a[1], Ab + 16 * ASTR + kk * 32);
            #pragma unroll
            for (int nip = 0; nip < 4; ++nip)
                ldsm4t(bq[nip], Bb + nip * 32 + kk * 16 * BSTR);
            #pragma unroll
            for (int mi = 0; mi < 2; ++mi)
                #pragma unroll
                for (int ni = 0; ni < 8; ++ni) {
                    const int nip = ni >> 1, h = (ni & 1) * 2;
                    mma_f16(acc[mi][ni], a[mi], bq[nip][h], bq[nip][h + 1]);
                }
        }

        // ---- off-path production for future segments
        if (s + 1 < NSEG) stsB((s + 1) & 1);        // convert+store B(s+1) (other buf)
        if (s + 2 < NSEG) { ldgB(s + 2); cpA(s + 2, (s + 2) % 3); }

        // expert-0 boundary: fold into out_acc, reset acc (thread-local)
        if (s == (NSEG / 2) - 1) {
            const float* bp = bb + (size_t)e0 * D + (size_t)tn * BN;
            #pragma unroll
            for (int mi = 0; mi < 2; ++mi)
                #pragma unroll
                for (int ni = 0; ni < 8; ++ni) {
                    int col = wn * 64 + ni * 8 + (lane & 3) * 2;
                    float b0v = bp[col], b1v = bp[col + 1];
                    out_acc[mi][ni][0] = w0 * fmaxf(acc[mi][ni][0] + b0v, 0.f);
                    out_acc[mi][ni][1] = w0 * fmaxf(acc[mi][ni][1] + b1v, 0.f);
                    out_acc[mi][ni][2] = w0 * fmaxf(acc[mi][ni][2] + b0v, 0.f);
                    out_acc[mi][ni][3] = w0 * fmaxf(acc[mi][ni][3] + b1v, 0.f);
                    acc[mi][ni][0] = 0.f; acc[mi][ni][1] = 0.f;
                    acc[mi][ni][2] = 0.f; acc[mi][ni][3] = 0.f;
                }
        }
    }

    // expert-1 fold + store
    {
        const float* bp = bb + (size_t)e1 * D + (size_t)tn * BN;
        float* ob = out + ((size_t)b * T + (size_t)tm * BM) * D + (size_t)tn * BN;
        #pragma unroll
        for (int mi = 0; mi < 2; ++mi)
            #pragma unroll
            for (int ni = 0; ni < 8; ++ni) {
                int col = wn * 64 + ni * 8 + (lane & 3) * 2;
                float b0v = bp[col], b1v = bp[col + 1];
                float v00 = out_acc[mi][ni][0] + w1 * fmaxf(acc[mi][ni][0] + b0v, 0.f);
                float v01 = out_acc[mi][ni][1] + w1 * fmaxf(acc[mi][ni][1] + b1v, 0.f);
                float v10 = out_acc[mi][ni][2] + w1 * fmaxf(acc[mi][ni][2] + b0v, 0.f);
                float v11 = out_acc[mi][ni][3] + w1 * fmaxf(acc[mi][ni][3] + b1v, 0.f);
                int r0 = wm * 32 + mi * 16 + (lane >> 2);
                *reinterpret_cast<float2*>(&ob[(size_t)r0 * D + col]) = make_float2(v00, v01);
                *reinterpret_cast<float2*>(&ob[(size_t)(r0 + 8) * D + col]) = make_float2(v10, v11);
            }
    }
}

extern "C" void kernel_launch(void* const* d_in, const int* in_sizes, int n_in,
                              void* d_out, int out_size) {
    const float* x   = (const float*)d_in[0];
    const float* w   = (const float*)d_in[1];
    const float* Wb  = (const float*)d_in[2];
    const float* bb  = (const float*)d_in[3];
    const void*  idx = (const void*)d_in[4];
    float* out = (float*)d_out;

    round_x_half<<<2048, 256>>>(x);

    cudaFuncSetAttribute(expertbank_kernel,
                         cudaFuncAttributeMaxDynamicSharedMemorySize, SMEM_BYTES);
    dim3 grid(D / BN, T / BM, Bdim);  // (8, 4, 8) = 256 blocks
    expertbank_kernel<<<grid, THREADS, SMEM_BYTES>>>(w, Wb, bb, idx, out);
}